// round 1
// baseline (speedup 1.0000x reference)
#include <cuda_runtime.h>
#include <cstdint>

// Input order (metadata.txt / setup_inputs dict order):
// 0:src[E,128] 1:dst[E,128] 2:edge_attr[E,64] 3:u[64,64]
// 4:W1[384,256] 5:b1[256] 6:g1[256] 7:be1[256]
// 8:W2[256,256] 9:b2[256] 10:g2[256] 11:be2[256] 12:batch[E] int32
// output: [E,256] float32

#define E_N 500000
#define X_  128
#define EA_ 64
#define U_  64
#define HS  256
#define CIN 384
#define BM  128
#define BN  128
#define BK  32
#define NTHREADS 256

// scratch: h (pre-BN1 output of layer 1), 500000*256 fp32 = 512 MB
__device__ float g_h[(size_t)E_N * HS];
__device__ float g_sum1[HS], g_sq1[HS], g_sum2[HS], g_sq2[HS];
__device__ float g_scale1[HS], g_shift1[HS];
__device__ float g_scale2[HS], g_shift2[HS];

__device__ __forceinline__ unsigned f2tf(float f) {
    unsigned u;
    asm("cvt.rna.tf32.f32 %0, %1;" : "=r"(u) : "f"(f));
    return u;
}

__device__ __forceinline__ void mma_tf32(float* c, const unsigned* a, const unsigned* b) {
    asm volatile(
        "mma.sync.aligned.m16n8k8.row.col.f32.tf32.tf32.f32 "
        "{%0,%1,%2,%3}, {%4,%5,%6,%7}, {%8,%9}, {%0,%1,%2,%3};\n"
        : "+f"(c[0]), "+f"(c[1]), "+f"(c[2]), "+f"(c[3])
        : "r"(a[0]), "r"(a[1]), "r"(a[2]), "r"(a[3]),
          "r"(b[0]), "r"(b[1]));
}

__global__ void zero_stats_kernel() {
    int i = threadIdx.x;
    if (i < HS) { g_sum1[i] = 0.f; g_sq1[i] = 0.f; g_sum2[i] = 0.f; g_sq2[i] = 0.f; }
}

// LAYER==1: A = gathered concat [src|dst|edge_attr|u[batch]] (K=384), writes g_h,
//           stats -> g_sum1/g_sq1
// LAYER==2: A = relu(g_h*scale1+shift1) (K=256), writes `out` (pre-BN2),
//           stats -> g_sum2/g_sq2
template <int LAYER>
__global__ __launch_bounds__(NTHREADS)
void gemm_kernel(const float* __restrict__ src, const float* __restrict__ dstf,
                 const float* __restrict__ ea,  const float* __restrict__ u,
                 const int*   __restrict__ batch,
                 const float* __restrict__ W,   const float* __restrict__ bias,
                 float* __restrict__ out)
{
    const int KB = (LAYER == 1) ? (CIN / BK) : (HS / BK);
    __shared__ __align__(16) unsigned As[BM][36];   // pad 36: conflict-free frag reads
    __shared__ __align__(16) unsigned Bs[BK][132];  // pad 132
    __shared__ float s_sum[BN], s_sq[BN];

    const int tid  = threadIdx.x;
    const int lane = tid & 31, wid = tid >> 5;
    const int warp_m = wid & 3, warp_n = wid >> 2;     // 4x2 warp grid, warp tile 32x64
    const int tileM = blockIdx.y, tileN = blockIdx.x;

    float acc[2][8][4];
#pragma unroll
    for (int i = 0; i < 2; i++)
#pragma unroll
        for (int j = 0; j < 8; j++)
#pragma unroll
            for (int k = 0; k < 4; k++) acc[i][j][k] = 0.f;

    const int ar  = tid >> 3;  // A: row 0..31 (x4), k-quad 0..7
    const int akq = tid & 7;
    const int bkr = tid >> 5;  // B: k-row 0..7 (x4), n-quad 0..31
    const int bnq = tid & 31;

    float* outp = (LAYER == 1) ? g_h : out;

    for (int kb = 0; kb < KB; ++kb) {
        __syncthreads();
        // ---- load A tile (gather + cvt to tf32) ----
#pragma unroll
        for (int i = 0; i < 4; ++i) {
            int rl = ar + i * 32;
            int e  = tileM * BM + rl;
            float4 v = make_float4(0.f, 0.f, 0.f, 0.f);
            if (e < E_N) {
                if (LAYER == 1) {
                    const float* p;
                    if (kb < 4)       p = src  + (size_t)e * X_  + kb * 32;
                    else if (kb < 8)  p = dstf + (size_t)e * X_  + (kb - 4) * 32;
                    else if (kb < 10) p = ea   + (size_t)e * EA_ + (kb - 8) * 32;
                    else              p = u    + (size_t)batch[e] * U_ + (kb - 10) * 32;
                    v = *(const float4*)(p + akq * 4);
                } else {
                    int c = kb * 32 + akq * 4;
                    float4 h = *(const float4*)(g_h + (size_t)e * HS + c);
                    v.x = fmaxf(h.x * g_scale1[c]     + g_shift1[c],     0.f);
                    v.y = fmaxf(h.y * g_scale1[c + 1] + g_shift1[c + 1], 0.f);
                    v.z = fmaxf(h.z * g_scale1[c + 2] + g_shift1[c + 2], 0.f);
                    v.w = fmaxf(h.w * g_scale1[c + 3] + g_shift1[c + 3], 0.f);
                }
            }
            uint4 t = make_uint4(f2tf(v.x), f2tf(v.y), f2tf(v.z), f2tf(v.w));
            *(uint4*)&As[rl][akq * 4] = t;
        }
        // ---- load B tile (W row-major [K,256]) ----
#pragma unroll
        for (int i = 0; i < 4; ++i) {
            int k = bkr + i * 8;
            float4 w = *(const float4*)(W + (size_t)(kb * 32 + k) * HS + tileN * BN + bnq * 4);
            uint4 t = make_uint4(f2tf(w.x), f2tf(w.y), f2tf(w.z), f2tf(w.w));
            *(uint4*)&Bs[k][bnq * 4] = t;
        }
        __syncthreads();

        const int lr = lane >> 2, lc = lane & 3;
#pragma unroll
        for (int kk = 0; kk < 4; ++kk) {
            unsigned a[2][4], b[8][2];
#pragma unroll
            for (int mi = 0; mi < 2; ++mi) {
                int r = warp_m * 32 + mi * 16 + lr;
                int c = kk * 8 + lc;
                a[mi][0] = As[r][c];
                a[mi][1] = As[r + 8][c];
                a[mi][2] = As[r][c + 4];
                a[mi][3] = As[r + 8][c + 4];
            }
#pragma unroll
            for (int ni = 0; ni < 8; ++ni) {
                int n = warp_n * 64 + ni * 8 + lr;
                b[ni][0] = Bs[kk * 8 + lc][n];
                b[ni][1] = Bs[kk * 8 + lc + 4][n];
            }
#pragma unroll
            for (int mi = 0; mi < 2; ++mi)
#pragma unroll
                for (int ni = 0; ni < 8; ++ni)
                    mma_tf32(acc[mi][ni], a[mi], b[ni]);
        }
    }

    // ---- epilogue: bias add, store, per-channel sum/sumsq reduction ----
    __syncthreads();
    if (tid < BN) { s_sum[tid] = 0.f; s_sq[tid] = 0.f; }
    __syncthreads();

    float* sumg = (LAYER == 1) ? g_sum1 : g_sum2;
    float* sqg  = (LAYER == 1) ? g_sq1  : g_sq2;

    const int lr  = lane >> 2;
    const int lc2 = (lane & 3) * 2;
#pragma unroll
    for (int ni = 0; ni < 8; ++ni) {
        int cl = warp_n * 64 + ni * 8 + lc2;   // local col (this thread owns cl, cl+1)
        int cg = tileN * BN + cl;
        float b0 = bias[cg], b1v = bias[cg + 1];
        float cs0 = 0.f, cs1 = 0.f, cq0 = 0.f, cq1 = 0.f;
#pragma unroll
        for (int mi = 0; mi < 2; ++mi) {
#pragma unroll
            for (int h = 0; h < 2; ++h) {
                int r = warp_m * 32 + mi * 16 + lr + h * 8;
                int e = tileM * BM + r;
                float v0 = acc[mi][ni][h * 2]     + b0;
                float v1 = acc[mi][ni][h * 2 + 1] + b1v;
                if (e < E_N) {
                    *(float2*)(outp + (size_t)e * HS + cg) = make_float2(v0, v1);
                    cs0 += v0; cs1 += v1;
                    cq0 += v0 * v0; cq1 += v1 * v1;
                }
            }
        }
        // reduce across the 8 lanes sharing this column (same lane&3)
#pragma unroll
        for (int off = 4; off < 32; off <<= 1) {
            cs0 += __shfl_xor_sync(0xffffffffu, cs0, off);
            cs1 += __shfl_xor_sync(0xffffffffu, cs1, off);
            cq0 += __shfl_xor_sync(0xffffffffu, cq0, off);
            cq1 += __shfl_xor_sync(0xffffffffu, cq1, off);
        }
        if (lr == 0) {
            atomicAdd(&s_sum[cl], cs0);     atomicAdd(&s_sum[cl + 1], cs1);
            atomicAdd(&s_sq[cl],  cq0);     atomicAdd(&s_sq[cl + 1],  cq1);
        }
    }
    __syncthreads();
    if (tid < BN) {
        atomicAdd(&sumg[tileN * BN + tid], s_sum[tid]);
        atomicAdd(&sqg[tileN * BN + tid],  s_sq[tid]);
    }
}

template <int LAYER>
__global__ void finalize_kernel(const float* __restrict__ gamma,
                                const float* __restrict__ beta) {
    int c = threadIdx.x;
    const float inv = 1.f / (float)E_N;
    float sm  = (LAYER == 1) ? g_sum1[c] : g_sum2[c];
    float sq  = (LAYER == 1) ? g_sq1[c]  : g_sq2[c];
    float m   = sm * inv;
    float var = sq * inv - m * m;
    float s   = gamma[c] * rsqrtf(var + 1e-5f);
    if (LAYER == 1) { g_scale1[c] = s; g_shift1[c] = beta[c] - m * s; }
    else            { g_scale2[c] = s; g_shift2[c] = beta[c] - m * s; }
}

__global__ void apply_bn2_kernel(float* __restrict__ out) {
    size_t i = (size_t)blockIdx.x * blockDim.x + threadIdx.x;
    const size_t n4 = (size_t)E_N * HS / 4;
    if (i < n4) {
        int c = (int)((i * 4) & (HS - 1));
        float4 v = ((float4*)out)[i];
        v.x = v.x * g_scale2[c]     + g_shift2[c];
        v.y = v.y * g_scale2[c + 1] + g_shift2[c + 1];
        v.z = v.z * g_scale2[c + 2] + g_shift2[c + 2];
        v.w = v.w * g_scale2[c + 3] + g_shift2[c + 3];
        ((float4*)out)[i] = v;
    }
}

extern "C" void kernel_launch(void* const* d_in, const int* in_sizes, int n_in,
                              void* d_out, int out_size) {
    const float* src  = (const float*)d_in[0];
    const float* dstf = (const float*)d_in[1];
    const float* ea   = (const float*)d_in[2];
    const float* u    = (const float*)d_in[3];
    const float* W1   = (const float*)d_in[4];
    const float* b1   = (const float*)d_in[5];
    const float* g1   = (const float*)d_in[6];
    const float* be1  = (const float*)d_in[7];
    const float* W2   = (const float*)d_in[8];
    const float* b2   = (const float*)d_in[9];
    const float* g2   = (const float*)d_in[10];
    const float* be2  = (const float*)d_in[11];
    const int*   batch = (const int*)d_in[12];
    float* out = (float*)d_out;

    dim3 grid(HS / BN, (E_N + BM - 1) / BM);  // (2, 3907)

    zero_stats_kernel<<<1, HS>>>();
    gemm_kernel<1><<<grid, NTHREADS>>>(src, dstf, ea, u, batch, W1, b1, nullptr);
    finalize_kernel<1><<<1, HS>>>(g1, be1);
    gemm_kernel<2><<<grid, NTHREADS>>>(nullptr, nullptr, nullptr, nullptr, nullptr,
                                       W2, b2, out);
    finalize_kernel<2><<<1, HS>>>(g2, be2);
    size_t n4 = (size_t)E_N * HS / 4;
    int ablocks = (int)((n4 + 255) / 256);
    apply_bn2_kernel<<<ablocks, 256>>>(out);
}

// round 4
// speedup vs baseline: 1.1976x; 1.1976x over previous
#include <cuda_runtime.h>
#include <cstdint>

// Inputs: 0:src[E,128] 1:dst[E,128] 2:edge_attr[E,64] 3:u[64,64]
// 4:W1[384,256] 5:b1 6:g1 7:be1 8:W2[256,256] 9:b2 10:g2 11:be2 12:batch[E]
// output: [E,256] fp32

#define E_N 500000
#define HS  256
#define CIN 384
#define BM  128
#define BK  32
#define NTH 512
#define STAGES 3
#define A_PITCH 36
#define B_PITCH 264
#define A_STAGE (BM * A_PITCH)   // 4608 floats
#define B_STAGE (BK * B_PITCH)   // 8448 floats

__device__ float g_h[(size_t)E_N * HS];   // layer-1 pre-BN output scratch (512 MB)
__device__ float g_sum1[HS], g_sq1[HS], g_sum2[HS], g_sq2[HS];
__device__ float g_scale1[HS], g_shift1[HS], g_scale2[HS], g_shift2[HS];

__device__ __forceinline__ unsigned f2tf(float f) {
    unsigned u;
    asm("cvt.rna.tf32.f32 %0, %1;" : "=r"(u) : "f"(f));
    return u;
}

__device__ __forceinline__ void mma_tf32(float* c, const unsigned* a, const unsigned* b) {
    asm volatile(
        "mma.sync.aligned.m16n8k8.row.col.f32.tf32.tf32.f32 "
        "{%0,%1,%2,%3}, {%4,%5,%6,%7}, {%8,%9}, {%0,%1,%2,%3};\n"
        : "+f"(c[0]), "+f"(c[1]), "+f"(c[2]), "+f"(c[3])
        : "r"(a[0]), "r"(a[1]), "r"(a[2]), "r"(a[3]),
          "r"(b[0]), "r"(b[1]));
}

__device__ __forceinline__ void cp16(float* sdst, const float* gsrc, bool p) {
    unsigned sa = (unsigned)__cvta_generic_to_shared(sdst);
    int sz = p ? 16 : 0;
    asm volatile("cp.async.cg.shared.global [%0], [%1], 16, %2;\n"
                 :: "r"(sa), "l"(gsrc), "r"(sz));
}
#define CP_COMMIT() asm volatile("cp.async.commit_group;\n")
#define CP_WAIT(n)  asm volatile("cp.async.wait_group %0;\n" :: "n"(n))

__global__ void zero_stats_kernel() {
    int i = threadIdx.x;
    if (i < HS) { g_sum1[i] = 0.f; g_sq1[i] = 0.f; g_sum2[i] = 0.f; g_sq2[i] = 0.f; }
}

template <int LAYER>
__device__ __forceinline__ void load_tiles(
    float* As, float* Bs, int kb, int tid, int tileM,
    const float* src, const float* dstf, const float* ea, const float* u,
    int bi0, int bi1, const float* W)
{
    // A tile: 128 rows x 32 cols = 1024 x 16B chunks, 2 per thread
#pragma unroll
    for (int j = 0; j < 2; ++j) {
        int ci  = tid + j * NTH;
        int row = ci >> 3;
        int c16 = (ci & 7) * 4;
        int e   = tileM * BM + row;
        bool p  = (e < E_N);
        const float* g;
        if (LAYER == 1) {
            if (kb < 4)       g = src  + (size_t)e * 128 + kb * 32 + c16;
            else if (kb < 8)  g = dstf + (size_t)e * 128 + (kb - 4) * 32 + c16;
            else if (kb < 10) g = ea   + (size_t)e * 64  + (kb - 8) * 32 + c16;
            else              g = u    + (size_t)(j ? bi1 : bi0) * 64 + (kb - 10) * 32 + c16;
        } else {
            g = g_h + (size_t)e * HS + kb * 32 + c16;
        }
        cp16(&As[row * A_PITCH + c16], g, p);
    }
    // B tile: 32 k-rows x 256 cols = 2048 x 16B chunks, 4 per thread
#pragma unroll
    for (int j = 0; j < 4; ++j) {
        int ci = tid + j * NTH;
        int kr = ci >> 6;
        int cc = (ci & 63) * 4;
        cp16(&Bs[kr * B_PITCH + cc], W + (size_t)(kb * BK + kr) * HS + cc, true);
    }
}

template <int LAYER>
__global__ __launch_bounds__(NTH, 1)
void gemm_kernel(const float* __restrict__ src, const float* __restrict__ dstf,
                 const float* __restrict__ ea,  const float* __restrict__ u,
                 const int*   __restrict__ batch,
                 const float* __restrict__ W,   const float* __restrict__ bias,
                 float* __restrict__ out)
{
    extern __shared__ float sm[];
    float* As      = sm;                        // STAGES * A_STAGE
    float* Bs      = sm + STAGES * A_STAGE;     // STAGES * B_STAGE
    float* s_scale = Bs + STAGES * B_STAGE;     // HS
    float* s_shift = s_scale + HS;              // HS
    float* s_sum   = s_shift + HS;              // HS
    float* s_sq    = s_sum + HS;                // HS

    const int tid  = threadIdx.x;
    const int lane = tid & 31, wid = tid >> 5;
    const int warp_m = wid & 3, warp_n = wid >> 2;  // 4x4 warps, warp tile 32x64
    const int tileM = blockIdx.x;
    const int KB = (LAYER == 1) ? (CIN / BK) : (HS / BK);

    int bi0 = 0, bi1 = 0;
    if (LAYER == 1) {
        int e0 = tileM * BM + (tid >> 3);
        int e1 = e0 + 64;
        bi0 = (e0 < E_N) ? batch[e0] : 0;
        bi1 = (e1 < E_N) ? batch[e1] : 0;
    }
    if (LAYER == 2 && tid < HS) { s_scale[tid] = g_scale1[tid]; s_shift[tid] = g_shift1[tid]; }
    if (tid < HS) { s_sum[tid] = 0.f; s_sq[tid] = 0.f; }

    // prologue: prefetch stages 0,1
    load_tiles<LAYER>(As, Bs, 0, tid, tileM, src, dstf, ea, u, bi0, bi1, W);
    CP_COMMIT();
    load_tiles<LAYER>(As + A_STAGE, Bs + B_STAGE, 1, tid, tileM, src, dstf, ea, u, bi0, bi1, W);
    CP_COMMIT();

    float acc[2][8][4];
#pragma unroll
    for (int i = 0; i < 2; i++)
#pragma unroll
        for (int j = 0; j < 8; j++)
#pragma unroll
            for (int k = 0; k < 4; k++) acc[i][j][k] = 0.f;

    const int lr = lane >> 2, lc = lane & 3;

    for (int kb = 0; kb < KB; ++kb) {
        if (kb + 2 < KB) CP_WAIT(1); else CP_WAIT(0);
        __syncthreads();
        if (kb + 2 < KB) {
            int ns = (kb + 2) % STAGES;
            load_tiles<LAYER>(As + ns * A_STAGE, Bs + ns * B_STAGE, kb + 2, tid, tileM,
                              src, dstf, ea, u, bi0, bi1, W);
            CP_COMMIT();
        }
        const float* as = As + (kb % STAGES) * A_STAGE;
        const float* bs = Bs + (kb % STAGES) * B_STAGE;
#pragma unroll
        for (int kk = 0; kk < 4; ++kk) {
            int c0 = kk * 8 + lc, c1 = c0 + 4;
            float s0 = 0.f, t0 = 0.f, s1 = 0.f, t1 = 0.f;
            if (LAYER == 2) {
                s0 = s_scale[kb * 32 + c0]; t0 = s_shift[kb * 32 + c0];
                s1 = s_scale[kb * 32 + c1]; t1 = s_shift[kb * 32 + c1];
            }
            unsigned a[2][4], b[8][2];
#pragma unroll
            for (int mi = 0; mi < 2; ++mi) {
                int r = warp_m * 32 + mi * 16 + lr;
                float v0 = as[r * A_PITCH + c0];
                float v1 = as[(r + 8) * A_PITCH + c0];
                float v2 = as[r * A_PITCH + c1];
                float v3 = as[(r + 8) * A_PITCH + c1];
                if (LAYER == 2) {
                    v0 = fmaxf(fmaf(v0, s0, t0), 0.f);
                    v1 = fmaxf(fmaf(v1, s0, t0), 0.f);
                    v2 = fmaxf(fmaf(v2, s1, t1), 0.f);
                    v3 = fmaxf(fmaf(v3, s1, t1), 0.f);
                }
                a[mi][0] = f2tf(v0); a[mi][1] = f2tf(v1);
                a[mi][2] = f2tf(v2); a[mi][3] = f2tf(v3);
            }
#pragma unroll
            for (int ni = 0; ni < 8; ++ni) {
                int n = warp_n * 64 + ni * 8 + lr;
                b[ni][0] = f2tf(bs[c0 * B_PITCH + n]);
                b[ni][1] = f2tf(bs[c1 * B_PITCH + n]);
            }
#pragma unroll
            for (int mi = 0; mi < 2; ++mi)
#pragma unroll
                for (int ni = 0; ni < 8; ++ni)
                    mma_tf32(acc[mi][ni], a[mi], b[ni]);
        }
    }

    // epilogue: bias add, store, per-channel sum/sumsq
    float* outp = (LAYER == 1) ? g_h : out;
    float* sumg = (LAYER == 1) ? g_sum1 : g_sum2;
    float* sqg  = (LAYER == 1) ? g_sq1  : g_sq2;

    const int lc2 = (lane & 3) * 2;
#pragma unroll
    for (int ni = 0; ni < 8; ++ni) {
        int cg = warp_n * 64 + ni * 8 + lc2;
        float b0 = bias[cg], b1v = bias[cg + 1];
        float cs0 = 0.f, cs1 = 0.f, cq0 = 0.f, cq1 = 0.f;
#pragma unroll
        for (int mi = 0; mi < 2; ++mi) {
#pragma unroll
            for (int h = 0; h < 2; ++h) {
                int r = warp_m * 32 + mi * 16 + lr + h * 8;
                int e = tileM * BM + r;
                float v0 = acc[mi][ni][h * 2]     + b0;
                float v1 = acc[mi][ni][h * 2 + 1] + b1v;
                if (e < E_N) {
                    *(float2*)(outp + (size_t)e * HS + cg) = make_float2(v0, v1);
                    cs0 += v0; cs1 += v1;
                    cq0 += v0 * v0; cq1 += v1 * v1;
                }
            }
        }
#pragma unroll
        for (int off = 4; off < 32; off <<= 1) {
            cs0 += __shfl_xor_sync(0xffffffffu, cs0, off);
            cs1 += __shfl_xor_sync(0xffffffffu, cs1, off);
            cq0 += __shfl_xor_sync(0xffffffffu, cq0, off);
            cq1 += __shfl_xor_sync(0xffffffffu, cq1, off);
        }
        if (lr == 0) {
            atomicAdd(&s_sum[cg], cs0);     atomicAdd(&s_sum[cg + 1], cs1);
            atomicAdd(&s_sq[cg],  cq0);     atomicAdd(&s_sq[cg + 1],  cq1);
        }
    }
    __syncthreads();
    if (tid < HS) {
        atomicAdd(&sumg[tid], s_sum[tid]);
        atomicAdd(&sqg[tid],  s_sq[tid]);
    }
}

template <int LAYER>
__global__ void finalize_kernel(const float* __restrict__ gamma,
                                const float* __restrict__ beta) {
    int c = threadIdx.x;
    const float inv = 1.f / (float)E_N;
    float sm  = (LAYER == 1) ? g_sum1[c] : g_sum2[c];
    float sq  = (LAYER == 1) ? g_sq1[c]  : g_sq2[c];
    float m   = sm * inv;
    float var = sq * inv - m * m;
    float s   = gamma[c] * rsqrtf(var + 1e-5f);
    if (LAYER == 1) { g_scale1[c] = s; g_shift1[c] = beta[c] - m * s; }
    else            { g_scale2[c] = s; g_shift2[c] = beta[c] - m * s; }
}

__global__ void apply_bn2_kernel(float* __restrict__ out) {
    size_t i = (size_t)blockIdx.x * blockDim.x + threadIdx.x;
    const size_t n4 = (size_t)E_N * HS / 4;
    if (i < n4) {
        int c = (int)((i * 4) & (HS - 1));
        float4 v = ((float4*)out)[i];
        v.x = v.x * g_scale2[c]     + g_shift2[c];
        v.y = v.y * g_scale2[c + 1] + g_shift2[c + 1];
        v.z = v.z * g_scale2[c + 2] + g_shift2[c + 2];
        v.w = v.w * g_scale2[c + 3] + g_shift2[c + 3];
        ((float4*)out)[i] = v;
    }
}

extern "C" void kernel_launch(void* const* d_in, const int* in_sizes, int n_in,
                              void* d_out, int out_size) {
    const float* src  = (const float*)d_in[0];
    const float* dstf = (const float*)d_in[1];
    const float* ea   = (const float*)d_in[2];
    const float* u    = (const float*)d_in[3];
    const float* W1   = (const float*)d_in[4];
    const float* b1   = (const float*)d_in[5];
    const float* g1   = (const float*)d_in[6];
    const float* be1  = (const float*)d_in[7];
    const float* W2   = (const float*)d_in[8];
    const float* b2   = (const float*)d_in[9];
    const float* g2   = (const float*)d_in[10];
    const float* be2  = (const float*)d_in[11];
    const int*   batch = (const int*)d_in[12];
    float* out = (float*)d_out;

    const int smem_bytes = (STAGES * A_STAGE + STAGES * B_STAGE + 4 * HS) * 4;
    cudaFuncSetAttribute(gemm_kernel<1>, cudaFuncAttributeMaxDynamicSharedMemorySize, smem_bytes);
    cudaFuncSetAttribute(gemm_kernel<2>, cudaFuncAttributeMaxDynamicSharedMemorySize, smem_bytes);

    const int grid = (E_N + BM - 1) / BM;  // 3907

    zero_stats_kernel<<<1, HS>>>();
    gemm_kernel<1><<<grid, NTH, smem_bytes>>>(src, dstf, ea, u, batch, W1, b1, nullptr);
    finalize_kernel<1><<<1, HS>>>(g1, be1);
    gemm_kernel<2><<<grid, NTH, smem_bytes>>>(nullptr, nullptr, nullptr, nullptr, batch,
                                              W2, b2, out);
    finalize_kernel<2><<<1, HS>>>(g2, be2);
    size_t n4 = (size_t)E_N * HS / 4;
    int ablocks = (int)((n4 + 255) / 256);
    apply_bn2_kernel<<<ablocks, 256>>>(out);
}

// round 14
// speedup vs baseline: 1.2560x; 1.0488x over previous
#include <cuda_runtime.h>
#include <cstdint>

// Inputs: 0:src[E,128] 1:dst[E,128] 2:edge_attr[E,64] 3:u[64,64]
// 4:W1[384,256] 5:b1 6:g1 7:be1 8:W2[256,256] 9:b2 10:g2 11:be2 12:batch[E]
// output: [E,256] fp32

#define E_N 500000
#define HS  256
#define CIN 384
#define BM  128
#define BK  32
#define NTH 512
#define STAGES 3
#define A_PITCH 36
#define B_PITCH 264
#define A_STAGE (BM * A_PITCH)   // 4608 words
#define B_STAGE (BK * B_PITCH)   // 8448 words

__device__ float    g_h[(size_t)E_N * HS];       // layer-1 pre-BN output (512 MB)
__device__ unsigned g_W1t[CIN * HS];             // W1 pre-converted to tf32 bits
__device__ unsigned g_W2t[HS * HS];              // W2 pre-converted to tf32 bits
__device__ float g_sum1[HS], g_sq1[HS], g_sum2[HS], g_sq2[HS];
__device__ float g_scale1[HS], g_shift1[HS], g_scale2[HS], g_shift2[HS];

__device__ __forceinline__ unsigned f2tf(float f) {
    unsigned u;
    asm("cvt.rna.tf32.f32 %0, %1;" : "=r"(u) : "f"(f));
    return u;
}

__device__ __forceinline__ void mma_tf32(float* c, const unsigned* a, const unsigned* b) {
    asm volatile(
        "mma.sync.aligned.m16n8k8.row.col.f32.tf32.tf32.f32 "
        "{%0,%1,%2,%3}, {%4,%5,%6,%7}, {%8,%9}, {%0,%1,%2,%3};\n"
        : "+f"(c[0]), "+f"(c[1]), "+f"(c[2]), "+f"(c[3])
        : "r"(a[0]), "r"(a[1]), "r"(a[2]), "r"(a[3]),
          "r"(b[0]), "r"(b[1]));
}

__device__ __forceinline__ void cp16(void* sdst, const void* gsrc, bool p) {
    unsigned sa = (unsigned)__cvta_generic_to_shared(sdst);
    int sz = p ? 16 : 0;
    asm volatile("cp.async.cg.shared.global [%0], [%1], 16, %2;\n"
                 :: "r"(sa), "l"(gsrc), "r"(sz));
}
#define CP_COMMIT() asm volatile("cp.async.commit_group;\n")
#define CP_WAIT(n)  asm volatile("cp.async.wait_group %0;\n" :: "n"(n))

// prep: zero stats + convert both weight matrices to tf32 bits
__global__ void prep_kernel(const float* __restrict__ W1, const float* __restrict__ W2) {
    int i = blockIdx.x * blockDim.x + threadIdx.x;
    if (i < HS) { g_sum1[i] = 0.f; g_sq1[i] = 0.f; g_sum2[i] = 0.f; g_sq2[i] = 0.f; }
    if (i < CIN * HS) g_W1t[i] = f2tf(W1[i]);
    if (i < HS * HS)  g_W2t[i] = f2tf(W2[i]);
}

template <int LAYER>
__device__ __forceinline__ void load_tiles(
    float* As, float* Bs, int kb, int tid, int tileM,
    const float* src, const float* dstf, const float* ea, const float* u,
    int bi0, int bi1)
{
    // device-side symbol access (host code must NOT pass __device__ symbols)
    const unsigned* Wt = (LAYER == 1) ? g_W1t : g_W2t;
    // A tile: 128 rows x 32 cols, 2x 16B per thread
#pragma unroll
    for (int j = 0; j < 2; ++j) {
        int ci  = tid + j * NTH;
        int row = ci >> 3;
        int c16 = (ci & 7) * 4;
        int e   = tileM * BM + row;
        bool p  = (e < E_N);
        const float* g;
        if (LAYER == 1) {
            if (kb < 4)       g = src  + (size_t)e * 128 + kb * 32 + c16;
            else if (kb < 8)  g = dstf + (size_t)e * 128 + (kb - 4) * 32 + c16;
            else if (kb < 10) g = ea   + (size_t)e * 64  + (kb - 8) * 32 + c16;
            else              g = u    + (size_t)(j ? bi1 : bi0) * 64 + (kb - 10) * 32 + c16;
        } else {
            g = g_h + (size_t)e * HS + kb * 32 + c16;
        }
        cp16(&As[row * A_PITCH + c16], g, p);
    }
    // B tile: 32 k-rows x 256 cols of tf32 bits, 4x 16B per thread
#pragma unroll
    for (int j = 0; j < 4; ++j) {
        int ci = tid + j * NTH;
        int kr = ci >> 6;
        int cc = (ci & 63) * 4;
        cp16(&Bs[kr * B_PITCH + cc], Wt + (size_t)(kb * BK + kr) * HS + cc, true);
    }
}

// In-smem A transform: fp32 -> tf32 bits (layer 1), BN1+ReLU then tf32 (layer 2).
// Each thread transforms exactly the elements it cp.async'd (self-visibility).
template <int LAYER>
__device__ __forceinline__ void transform_A(float* As, int kb, int tid,
                                            const float* s_scale, const float* s_shift)
{
#pragma unroll
    for (int j = 0; j < 2; ++j) {
        int ci  = tid + j * NTH;
        int row = ci >> 3;
        int c   = (ci & 7) * 4;
        float4 v = *(float4*)&As[row * A_PITCH + c];
        if (LAYER == 2) {
            int cc = kb * 32 + c;
            v.x = fmaxf(fmaf(v.x, s_scale[cc],     s_shift[cc]),     0.f);
            v.y = fmaxf(fmaf(v.y, s_scale[cc + 1], s_shift[cc + 1]), 0.f);
            v.z = fmaxf(fmaf(v.z, s_scale[cc + 2], s_shift[cc + 2]), 0.f);
            v.w = fmaxf(fmaf(v.w, s_scale[cc + 3], s_shift[cc + 3]), 0.f);
        }
        uint4 t = make_uint4(f2tf(v.x), f2tf(v.y), f2tf(v.z), f2tf(v.w));
        *(uint4*)&As[row * A_PITCH + c] = t;
    }
}

template <int LAYER>
__global__ __launch_bounds__(NTH, 1)
void gemm_kernel(const float* __restrict__ src, const float* __restrict__ dstf,
                 const float* __restrict__ ea,  const float* __restrict__ u,
                 const int*   __restrict__ batch,
                 const float* __restrict__ bias,
                 float* __restrict__ out)
{
    extern __shared__ float sm[];
    float* As      = sm;                        // STAGES * A_STAGE
    float* Bs      = sm + STAGES * A_STAGE;     // STAGES * B_STAGE
    float* s_scale = Bs + STAGES * B_STAGE;     // HS
    float* s_shift = s_scale + HS;              // HS
    float* s_sum   = s_shift + HS;              // HS
    float* s_sq    = s_sum + HS;                // HS

    const int tid  = threadIdx.x;
    const int lane = tid & 31, wid = tid >> 5;
    const int warp_m = wid & 3, warp_n = wid >> 2;  // 4x4 warps, warp tile 32x64
    const int tileM = blockIdx.x;
    const int KB = (LAYER == 1) ? (CIN / BK) : (HS / BK);

    int bi0 = 0, bi1 = 0;
    if (LAYER == 1) {
        int e0 = tileM * BM + (tid >> 3);
        int e1 = e0 + 64;
        bi0 = (e0 < E_N) ? batch[e0] : 0;
        bi1 = (e1 < E_N) ? batch[e1] : 0;
    }
    if (LAYER == 2 && tid < HS) { s_scale[tid] = g_scale1[tid]; s_shift[tid] = g_shift1[tid]; }
    if (tid < HS) { s_sum[tid] = 0.f; s_sq[tid] = 0.f; }

    // prologue: prefetch stages 0,1; transform stage 0
    load_tiles<LAYER>(As, Bs, 0, tid, tileM, src, dstf, ea, u, bi0, bi1);
    CP_COMMIT();
    load_tiles<LAYER>(As + A_STAGE, Bs + B_STAGE, 1, tid, tileM, src, dstf, ea, u, bi0, bi1);
    CP_COMMIT();

    float acc[2][8][4];
#pragma unroll
    for (int i = 0; i < 2; i++)
#pragma unroll
        for (int j = 0; j < 8; j++)
#pragma unroll
            for (int k = 0; k < 4; k++) acc[i][j][k] = 0.f;

    CP_WAIT(1);                 // stage 0 landed (stage 1 may be in flight)
    __syncthreads();            // also covers s_scale/s_shift visibility
    transform_A<LAYER>(As, 0, tid, s_scale, s_shift);

    const int lr = lane >> 2, lc = lane & 3;

    for (int kb = 0; kb < KB; ++kb) {
        // separates: transform(kb) [prev iter] -> compute(kb);
        //            compute(kb-1) [prev iter] -> cp.async reuse of its buffer
        __syncthreads();
        if (kb + 2 < KB) {
            int ns = (kb + 2) % STAGES;
            load_tiles<LAYER>(As + ns * A_STAGE, Bs + ns * B_STAGE, kb + 2, tid, tileM,
                              src, dstf, ea, u, bi0, bi1);
            CP_COMMIT();
        }
        if (kb + 2 < KB) CP_WAIT(1); else CP_WAIT(0);   // stage kb+1 landed
        if (kb + 1 < KB)
            transform_A<LAYER>(As + ((kb + 1) % STAGES) * A_STAGE, kb + 1, tid,
                               s_scale, s_shift);

        const unsigned* as = (const unsigned*)(As + (kb % STAGES) * A_STAGE);
        const unsigned* bs = (const unsigned*)(Bs + (kb % STAGES) * B_STAGE);
#pragma unroll
        for (int kk = 0; kk < 4; ++kk) {
            int c0 = kk * 8 + lc, c1 = c0 + 4;
            unsigned a[2][4], b[8][2];
#pragma unroll
            for (int mi = 0; mi < 2; ++mi) {
                int r = warp_m * 32 + mi * 16 + lr;
                a[mi][0] = as[r * A_PITCH + c0];
                a[mi][1] = as[(r + 8) * A_PITCH + c0];
                a[mi][2] = as[r * A_PITCH + c1];
                a[mi][3] = as[(r + 8) * A_PITCH + c1];
            }
#pragma unroll
            for (int ni = 0; ni < 8; ++ni) {
                int n = warp_n * 64 + ni * 8 + lr;
                b[ni][0] = bs[c0 * B_PITCH + n];
                b[ni][1] = bs[c1 * B_PITCH + n];
            }
#pragma unroll
            for (int mi = 0; mi < 2; ++mi)
#pragma unroll
                for (int ni = 0; ni < 8; ++ni)
                    mma_tf32(acc[mi][ni], a[mi], b[ni]);
        }
    }

    // epilogue: bias add, store, per-channel sum/sumsq
    float* outp = (LAYER == 1) ? g_h : out;
    float* sumg = (LAYER == 1) ? g_sum1 : g_sum2;
    float* sqg  = (LAYER == 1) ? g_sq1  : g_sq2;

    const int lc2 = (lane & 3) * 2;
#pragma unroll
    for (int ni = 0; ni < 8; ++ni) {
        int cg = warp_n * 64 + ni * 8 + lc2;
        float b0 = bias[cg], b1v = bias[cg + 1];
        float cs0 = 0.f, cs1 = 0.f, cq0 = 0.f, cq1 = 0.f;
#pragma unroll
        for (int mi = 0; mi < 2; ++mi) {
#pragma unroll
            for (int h = 0; h < 2; ++h) {
                int r = warp_m * 32 + mi * 16 + lr + h * 8;
                int e = tileM * BM + r;
                float v0 = acc[mi][ni][h * 2]     + b0;
                float v1 = acc[mi][ni][h * 2 + 1] + b1v;
                if (e < E_N) {
                    *(float2*)(outp + (size_t)e * HS + cg) = make_float2(v0, v1);
                    cs0 += v0; cs1 += v1;
                    cq0 += v0 * v0; cq1 += v1 * v1;
                }
            }
        }
#pragma unroll
        for (int off = 4; off < 32; off <<= 1) {
            cs0 += __shfl_xor_sync(0xffffffffu, cs0, off);
            cs1 += __shfl_xor_sync(0xffffffffu, cs1, off);
            cq0 += __shfl_xor_sync(0xffffffffu, cq0, off);
            cq1 += __shfl_xor_sync(0xffffffffu, cq1, off);
        }
        if (lr == 0) {
            atomicAdd(&s_sum[cg], cs0);     atomicAdd(&s_sum[cg + 1], cs1);
            atomicAdd(&s_sq[cg],  cq0);     atomicAdd(&s_sq[cg + 1],  cq1);
        }
    }
    __syncthreads();
    if (tid < HS) {
        atomicAdd(&sumg[tid], s_sum[tid]);
        atomicAdd(&sqg[tid],  s_sq[tid]);
    }
}

template <int LAYER>
__global__ void finalize_kernel(const float* __restrict__ gamma,
                                const float* __restrict__ beta) {
    int c = threadIdx.x;
    const float inv = 1.f / (float)E_N;
    float sm  = (LAYER == 1) ? g_sum1[c] : g_sum2[c];
    float sq  = (LAYER == 1) ? g_sq1[c]  : g_sq2[c];
    float m   = sm * inv;
    float var = sq * inv - m * m;
    float s   = gamma[c] * rsqrtf(var + 1e-5f);
    if (LAYER == 1) { g_scale1[c] = s; g_shift1[c] = beta[c] - m * s; }
    else            { g_scale2[c] = s; g_shift2[c] = beta[c] - m * s; }
}

__global__ void apply_bn2_kernel(float* __restrict__ out) {
    size_t i = (size_t)blockIdx.x * blockDim.x + threadIdx.x;
    const size_t n4 = (size_t)E_N * HS / 4;
    if (i < n4) {
        int c = (int)((i * 4) & (HS - 1));
        float4 v = ((float4*)out)[i];
        v.x = v.x * g_scale2[c]     + g_shift2[c];
        v.y = v.y * g_scale2[c + 1] + g_shift2[c + 1];
        v.z = v.z * g_scale2[c + 2] + g_shift2[c + 2];
        v.w = v.w * g_scale2[c + 3] + g_shift2[c + 3];
        ((float4*)out)[i] = v;
    }
}

extern "C" void kernel_launch(void* const* d_in, const int* in_sizes, int n_in,
                              void* d_out, int out_size) {
    const float* src  = (const float*)d_in[0];
    const float* dstf = (const float*)d_in[1];
    const float* ea   = (const float*)d_in[2];
    const float* u    = (const float*)d_in[3];
    const float* W1   = (const float*)d_in[4];
    const float* b1   = (const float*)d_in[5];
    const float* g1   = (const float*)d_in[6];
    const float* be1  = (const float*)d_in[7];
    const float* W2   = (const float*)d_in[8];
    const float* b2   = (const float*)d_in[9];
    const float* g2   = (const float*)d_in[10];
    const float* be2  = (const float*)d_in[11];
    const int*   batch = (const int*)d_in[12];
    float* out = (float*)d_out;

    const int smem_bytes = (STAGES * A_STAGE + STAGES * B_STAGE + 4 * HS) * 4;
    cudaFuncSetAttribute(gemm_kernel<1>, cudaFuncAttributeMaxDynamicSharedMemorySize, smem_bytes);
    cudaFuncSetAttribute(gemm_kernel<2>, cudaFuncAttributeMaxDynamicSharedMemorySize, smem_bytes);

    const int grid = (E_N + BM - 1) / BM;  // 3907

    prep_kernel<<<(CIN * HS + 255) / 256, 256>>>(W1, W2);
    gemm_kernel<1><<<grid, NTH, smem_bytes>>>(src, dstf, ea, u, batch, b1, nullptr);
    finalize_kernel<1><<<1, HS>>>(g1, be1);
    gemm_kernel<2><<<grid, NTH, smem_bytes>>>(nullptr, nullptr, nullptr, nullptr, batch,
                                              b2, out);
    finalize_kernel<2><<<1, HS>>>(g2, be2);
    size_t n4 = (size_t)E_N * HS / 4;
    int ablocks = (int)((n4 + 255) / 256);
    apply_bn2_kernel<<<ablocks, 256>>>(out);
}